// round 16
// baseline (speedup 1.0000x reference)
#include <cuda_runtime.h>
#include <cstdint>

#define N_NODES 100000
#define N_EDGES 1250000
#define D 64
#define NB 391              // ceil(100000/256)

// transform tiling
#define T_TPB 256
#define BLOCK_ROWS 256
#define KT 16
#define HS 380

// Scratch
__device__ float g_feat[(size_t)N_NODES * D];   // h @ W^T (25.6 MB)
__device__ int   deg_cnt[N_NODES];              // degree, then placement cursor
__device__ int   offs[N_NODES + 1];             // CSR offsets
__device__ int   partials[512];                 // block partial sums (padded)
__device__ int2  edge_s[N_EDGES];               // binned (src, bitcast e)

// Side stream + fork/join events, created once before any harness checkpoint.
static cudaStream_t g_side = nullptr;
static cudaEvent_t  g_fork = nullptr, g_join = nullptr;
namespace {
struct StreamInit {
    StreamInit() {
        cudaStreamCreateWithFlags(&g_side, cudaStreamNonBlocking);
        cudaEventCreateWithFlags(&g_fork, cudaEventDisableTiming);
        cudaEventCreateWithFlags(&g_join, cudaEventDisableTiming);
    }
};
StreamInit g_stream_init;
}

// ---------------------------------------------------------------------------
// CSR build (side stream)
// ---------------------------------------------------------------------------
__global__ void zero_deg_kernel() {
    int i = blockIdx.x * 256 + threadIdx.x;
    if (i < N_NODES) deg_cnt[i] = 0;
    if (i < 512) partials[i] = 0;
}

__global__ void hist_kernel(const int* __restrict__ dst) {
    int e = blockIdx.x * 256 + threadIdx.x;
    if (e < N_EDGES) atomicAdd(&deg_cnt[dst[e]], 1);
}

__global__ void partial_kernel() {
    __shared__ int s[256];
    int i = blockIdx.x * 256 + threadIdx.x;
    s[threadIdx.x] = (i < N_NODES) ? deg_cnt[i] : 0;
    __syncthreads();
    for (int off = 128; off > 0; off >>= 1) {
        if (threadIdx.x < off) s[threadIdx.x] += s[threadIdx.x + off];
        __syncthreads();
    }
    if (threadIdx.x == 0) partials[blockIdx.x] = s[0];
}

__global__ void scan_partials_kernel() {
    __shared__ int s[512];
    int tid = threadIdx.x;
    int v = partials[tid];                 // padded to 512 with zeros
    s[tid] = v;
    __syncthreads();
    for (int off = 1; off < 512; off <<= 1) {
        int t = (tid >= off) ? s[tid - off] : 0;
        __syncthreads();
        s[tid] += t;
        __syncthreads();
    }
    partials[tid] = s[tid] - v;            // exclusive
}

__global__ void offsets_kernel() {
    __shared__ int s[256];
    int tid = threadIdx.x;
    int i = blockIdx.x * 256 + tid;
    int v = (i < N_NODES) ? deg_cnt[i] : 0;
    s[tid] = v;
    __syncthreads();
    for (int off = 1; off < 256; off <<= 1) {
        int t = (tid >= off) ? s[tid - off] : 0;
        __syncthreads();
        s[tid] += t;
        __syncthreads();
    }
    int ex = s[tid] - v + partials[blockIdx.x];
    if (i < N_NODES) {
        offs[i] = ex;
        deg_cnt[i] = ex;                   // placement cursor
    }
    if (blockIdx.x == 0 && tid == 0) offs[N_NODES] = N_EDGES;
}

__global__ void place_kernel(const float* __restrict__ e,
                             const int* __restrict__ src,
                             const int* __restrict__ dst) {
    int i = blockIdx.x * 256 + threadIdx.x;
    if (i >= N_EDGES) return;
    int d   = dst[i];
    int pos = atomicAdd(&deg_cnt[d], 1);
    edge_s[pos] = make_int2(src[i], __float_as_int(e[i]));
}

// ---------------------------------------------------------------------------
// g = h @ W^T  (register-tiled f32x2, conflict-free smem layouts)
// ---------------------------------------------------------------------------
__global__ __launch_bounds__(T_TPB, 2) void transform_kernel(
        const float* __restrict__ h, const float* __restrict__ W) {
    __shared__ float Wt[D * D];
    __shared__ float hT[KT * HS];

    const int tid = threadIdx.x;

    for (int i = tid; i < D * D; i += T_TPB) {
        int o = i >> 6, k = i & 63;
        int u = o >> 2, el = o & 3;
        int p = ((u & 1) << 3) | (u >> 1);
        Wt[k * 64 + p * 4 + el] = W[i];
    }

    const int warp = tid >> 5;
    const int lane = tid & 31;
    const int cg   = lane & 7;
    const int rg   = warp * 4 + (lane >> 3);
    const int row0 = blockIdx.x * BLOCK_ROWS + rg * 8;
    const int rbp  = rg * 12;

    unsigned long long acc[8][4];
#pragma unroll
    for (int i = 0; i < 8; i++)
#pragma unroll
        for (int p = 0; p < 4; p++) acc[i][p] = 0ULL;

    const int base_row = blockIdx.x * BLOCK_ROWS;

    for (int kp = 0; kp < D / KT; kp++) {
        __syncthreads();
#pragma unroll
        for (int it = 0; it < 4; it++) {
            int gi  = tid + it * T_TPB;
            int row = gi & 255;
            int c4  = gi >> 8;
            int grow = base_row + row;
            if (grow > N_NODES - 1) grow = N_NODES - 1;
            float4 hv = *reinterpret_cast<const float4*>(
                &h[(size_t)grow * D + kp * KT + c4 * 4]);
            int rp = row + (row >> 3) * 4;
            hT[(c4 * 4 + 0) * HS + rp] = hv.x;
            hT[(c4 * 4 + 1) * HS + rp] = hv.y;
            hT[(c4 * 4 + 2) * HS + rp] = hv.z;
            hT[(c4 * 4 + 3) * HS + rp] = hv.w;
        }
        __syncthreads();

#pragma unroll 4
        for (int kl = 0; kl < KT; kl++) {
            const int k = kp * KT + kl;
            float4 ha = *reinterpret_cast<const float4*>(&hT[kl * HS + rbp]);
            float4 hb = *reinterpret_cast<const float4*>(&hT[kl * HS + rbp + 4]);
            unsigned long long h2[8];
            asm("mov.b64 %0, {%1, %1};" : "=l"(h2[0]) : "r"(__float_as_uint(ha.x)));
            asm("mov.b64 %0, {%1, %1};" : "=l"(h2[1]) : "r"(__float_as_uint(ha.y)));
            asm("mov.b64 %0, {%1, %1};" : "=l"(h2[2]) : "r"(__float_as_uint(ha.z)));
            asm("mov.b64 %0, {%1, %1};" : "=l"(h2[3]) : "r"(__float_as_uint(ha.w)));
            asm("mov.b64 %0, {%1, %1};" : "=l"(h2[4]) : "r"(__float_as_uint(hb.x)));
            asm("mov.b64 %0, {%1, %1};" : "=l"(h2[5]) : "r"(__float_as_uint(hb.y)));
            asm("mov.b64 %0, {%1, %1};" : "=l"(h2[6]) : "r"(__float_as_uint(hb.z)));
            asm("mov.b64 %0, {%1, %1};" : "=l"(h2[7]) : "r"(__float_as_uint(hb.w)));

            ulonglong2 w0 = *reinterpret_cast<const ulonglong2*>(
                &Wt[k * 64 + (cg << 2)]);
            ulonglong2 w1 = *reinterpret_cast<const ulonglong2*>(
                &Wt[k * 64 + ((8 + cg) << 2)]);
#pragma unroll
            for (int i = 0; i < 8; i++) {
                asm("fma.rn.f32x2 %0, %1, %2, %0;"
                    : "+l"(acc[i][0]) : "l"(h2[i]), "l"(w0.x));
                asm("fma.rn.f32x2 %0, %1, %2, %0;"
                    : "+l"(acc[i][1]) : "l"(h2[i]), "l"(w0.y));
                asm("fma.rn.f32x2 %0, %1, %2, %0;"
                    : "+l"(acc[i][2]) : "l"(h2[i]), "l"(w1.x));
                asm("fma.rn.f32x2 %0, %1, %2, %0;"
                    : "+l"(acc[i][3]) : "l"(h2[i]), "l"(w1.y));
            }
        }
    }

#pragma unroll
    for (int i = 0; i < 8; i++) {
        int row = row0 + i;
        if (row < N_NODES) {
            float* gp = &g_feat[(size_t)row * D + cg * 8];
            reinterpret_cast<ulonglong2*>(gp)[0] = make_ulonglong2(acc[i][0], acc[i][1]);
            reinterpret_cast<ulonglong2*>(gp)[1] = make_ulonglong2(acc[i][2], acc[i][3]);
        }
    }
}

// ---------------------------------------------------------------------------
// Aggregate (R12 layout, unroll-4): out[n] = b + sum_{edges->n} g[src]*e.
// 16 threads per node, thread = (node, quad). 4 independent gathers in
// flight per iteration (MLP=4).
// ---------------------------------------------------------------------------
__global__ __launch_bounds__(256) void aggregate_kernel(
        const float* __restrict__ bias, float* __restrict__ out) {
    int t = blockIdx.x * 256 + threadIdx.x;       // grid exactly N_NODES*16
    int node = t >> 4;
    int q    = (t & 15) * 4;

    float4 acc = __ldg(reinterpret_cast<const float4*>(&bias[q]));

    int i   = offs[node];
    int end = offs[node + 1];

    for (; i + 4 <= end; i += 4) {
        int2 p0 = edge_s[i];
        int2 p1 = edge_s[i + 1];
        int2 p2 = edge_s[i + 2];
        int2 p3 = edge_s[i + 3];
        const float4 g0 = *reinterpret_cast<const float4*>(
            &g_feat[(size_t)p0.x * D + q]);
        const float4 g1 = *reinterpret_cast<const float4*>(
            &g_feat[(size_t)p1.x * D + q]);
        const float4 g2 = *reinterpret_cast<const float4*>(
            &g_feat[(size_t)p2.x * D + q]);
        const float4 g3 = *reinterpret_cast<const float4*>(
            &g_feat[(size_t)p3.x * D + q]);
        float e0 = __int_as_float(p0.y), e1 = __int_as_float(p1.y);
        float e2 = __int_as_float(p2.y), e3 = __int_as_float(p3.y);
        acc.x = fmaf(g0.x, e0, acc.x); acc.y = fmaf(g0.y, e0, acc.y);
        acc.z = fmaf(g0.z, e0, acc.z); acc.w = fmaf(g0.w, e0, acc.w);
        acc.x = fmaf(g1.x, e1, acc.x); acc.y = fmaf(g1.y, e1, acc.y);
        acc.z = fmaf(g1.z, e1, acc.z); acc.w = fmaf(g1.w, e1, acc.w);
        acc.x = fmaf(g2.x, e2, acc.x); acc.y = fmaf(g2.y, e2, acc.y);
        acc.z = fmaf(g2.z, e2, acc.z); acc.w = fmaf(g2.w, e2, acc.w);
        acc.x = fmaf(g3.x, e3, acc.x); acc.y = fmaf(g3.y, e3, acc.y);
        acc.z = fmaf(g3.z, e3, acc.z); acc.w = fmaf(g3.w, e3, acc.w);
    }
    if (i + 2 <= end) {
        int2 p0 = edge_s[i];
        int2 p1 = edge_s[i + 1];
        const float4 g0 = *reinterpret_cast<const float4*>(
            &g_feat[(size_t)p0.x * D + q]);
        const float4 g1 = *reinterpret_cast<const float4*>(
            &g_feat[(size_t)p1.x * D + q]);
        float e0 = __int_as_float(p0.y), e1 = __int_as_float(p1.y);
        acc.x = fmaf(g0.x, e0, acc.x); acc.y = fmaf(g0.y, e0, acc.y);
        acc.z = fmaf(g0.z, e0, acc.z); acc.w = fmaf(g0.w, e0, acc.w);
        acc.x = fmaf(g1.x, e1, acc.x); acc.y = fmaf(g1.y, e1, acc.y);
        acc.z = fmaf(g1.z, e1, acc.z); acc.w = fmaf(g1.w, e1, acc.w);
        i += 2;
    }
    if (i < end) {
        int2 p0 = edge_s[i];
        const float4 g0 = *reinterpret_cast<const float4*>(
            &g_feat[(size_t)p0.x * D + q]);
        float e0 = __int_as_float(p0.y);
        acc.x = fmaf(g0.x, e0, acc.x); acc.y = fmaf(g0.y, e0, acc.y);
        acc.z = fmaf(g0.z, e0, acc.z); acc.w = fmaf(g0.w, e0, acc.w);
    }

    *reinterpret_cast<float4*>(&out[(size_t)node * D + q]) = acc;
}

// ---------------------------------------------------------------------------
extern "C" void kernel_launch(void* const* d_in, const int* in_sizes, int n_in,
                              void* d_out, int out_size) {
    const float* h   = (const float*)d_in[0];
    const float* e   = (const float*)d_in[1];
    const int*   src = (const int*)d_in[2];
    const int*   dst = (const int*)d_in[3];
    const float* W   = (const float*)d_in[4];
    const float* b   = (const float*)d_in[5];
    float*       out = (float*)d_out;

    const int eb = (N_EDGES + 255) / 256;          // 4883

    // Fork: CSR build on side stream, transform on main stream (independent).
    cudaEventRecord(g_fork, 0);
    cudaStreamWaitEvent(g_side, g_fork, 0);

    zero_deg_kernel<<<NB, 256, 0, g_side>>>();
    hist_kernel<<<eb, 256, 0, g_side>>>(dst);
    partial_kernel<<<NB, 256, 0, g_side>>>();
    scan_partials_kernel<<<1, 512, 0, g_side>>>();
    offsets_kernel<<<NB, 256, 0, g_side>>>();
    place_kernel<<<eb, 256, 0, g_side>>>(e, src, dst);
    cudaEventRecord(g_join, g_side);

    // g = h @ W^T  (main stream, overlaps with CSR build)
    transform_kernel<<<NB, T_TPB>>>(h, W);

    // Join, then aggregate: out = b + segment_sum(g[src] * e)
    cudaStreamWaitEvent(0, g_join, 0);
    aggregate_kernel<<<(N_NODES * 16) / 256, 256>>>(b, out);
}

// round 17
// speedup vs baseline: 1.3232x; 1.3232x over previous
#include <cuda_runtime.h>
#include <cuda_fp16.h>
#include <cstdint>

#define N_NODES 100000
#define N_EDGES 1250000
#define D 64
#define NB 391              // ceil(100000/256)

// transform tiling
#define T_TPB 256
#define BLOCK_ROWS 256
#define KT 16
#define HS 380

// Scratch
__device__ __half g_feat[(size_t)N_NODES * D];  // h @ W^T in fp16 (12.8 MB)
__device__ int    deg_cnt[N_NODES];             // degree, then placement cursor
__device__ int    offs[N_NODES + 1];            // CSR offsets
__device__ int    partials[512];                // block partial sums (padded)
__device__ int2   edge_s[N_EDGES];              // binned (src, bitcast e)

// Side stream + fork/join events, created once before any harness checkpoint.
static cudaStream_t g_side = nullptr;
static cudaEvent_t  g_fork = nullptr, g_join = nullptr;
namespace {
struct StreamInit {
    StreamInit() {
        cudaStreamCreateWithFlags(&g_side, cudaStreamNonBlocking);
        cudaEventCreateWithFlags(&g_fork, cudaEventDisableTiming);
        cudaEventCreateWithFlags(&g_join, cudaEventDisableTiming);
    }
};
StreamInit g_stream_init;
}

// ---------------------------------------------------------------------------
// CSR build (side stream)
// ---------------------------------------------------------------------------
__global__ void zero_deg_kernel() {
    int i = blockIdx.x * 256 + threadIdx.x;
    if (i < N_NODES) deg_cnt[i] = 0;
    if (i < 512) partials[i] = 0;
}

__global__ void hist_kernel(const int* __restrict__ dst) {
    int e = blockIdx.x * 256 + threadIdx.x;
    if (e < N_EDGES) atomicAdd(&deg_cnt[dst[e]], 1);
}

__global__ void partial_kernel() {
    __shared__ int s[256];
    int i = blockIdx.x * 256 + threadIdx.x;
    s[threadIdx.x] = (i < N_NODES) ? deg_cnt[i] : 0;
    __syncthreads();
    for (int off = 128; off > 0; off >>= 1) {
        if (threadIdx.x < off) s[threadIdx.x] += s[threadIdx.x + off];
        __syncthreads();
    }
    if (threadIdx.x == 0) partials[blockIdx.x] = s[0];
}

__global__ void scan_partials_kernel() {
    __shared__ int s[512];
    int tid = threadIdx.x;
    int v = partials[tid];                 // padded to 512 with zeros
    s[tid] = v;
    __syncthreads();
    for (int off = 1; off < 512; off <<= 1) {
        int t = (tid >= off) ? s[tid - off] : 0;
        __syncthreads();
        s[tid] += t;
        __syncthreads();
    }
    partials[tid] = s[tid] - v;            // exclusive
}

__global__ void offsets_kernel() {
    __shared__ int s[256];
    int tid = threadIdx.x;
    int i = blockIdx.x * 256 + tid;
    int v = (i < N_NODES) ? deg_cnt[i] : 0;
    s[tid] = v;
    __syncthreads();
    for (int off = 1; off < 256; off <<= 1) {
        int t = (tid >= off) ? s[tid - off] : 0;
        __syncthreads();
        s[tid] += t;
        __syncthreads();
    }
    int ex = s[tid] - v + partials[blockIdx.x];
    if (i < N_NODES) {
        offs[i] = ex;
        deg_cnt[i] = ex;                   // placement cursor
    }
    if (blockIdx.x == 0 && tid == 0) offs[N_NODES] = N_EDGES;
}

__global__ void place_kernel(const float* __restrict__ e,
                             const int* __restrict__ src,
                             const int* __restrict__ dst) {
    int i = blockIdx.x * 256 + threadIdx.x;
    if (i >= N_EDGES) return;
    int d   = dst[i];
    int pos = atomicAdd(&deg_cnt[d], 1);
    edge_s[pos] = make_int2(src[i], __float_as_int(e[i]));
}

// ---------------------------------------------------------------------------
// g = h @ W^T  (register-tiled f32x2, conflict-free smem layouts).
// Epilogue converts fp32 accumulators to fp16 (one uint4 store per row chunk).
// ---------------------------------------------------------------------------
__global__ __launch_bounds__(T_TPB, 2) void transform_kernel(
        const float* __restrict__ h, const float* __restrict__ W) {
    __shared__ float Wt[D * D];
    __shared__ float hT[KT * HS];

    const int tid = threadIdx.x;

    for (int i = tid; i < D * D; i += T_TPB) {
        int o = i >> 6, k = i & 63;
        int u = o >> 2, el = o & 3;
        int p = ((u & 1) << 3) | (u >> 1);
        Wt[k * 64 + p * 4 + el] = W[i];
    }

    const int warp = tid >> 5;
    const int lane = tid & 31;
    const int cg   = lane & 7;
    const int rg   = warp * 4 + (lane >> 3);
    const int row0 = blockIdx.x * BLOCK_ROWS + rg * 8;
    const int rbp  = rg * 12;

    unsigned long long acc[8][4];
#pragma unroll
    for (int i = 0; i < 8; i++)
#pragma unroll
        for (int p = 0; p < 4; p++) acc[i][p] = 0ULL;

    const int base_row = blockIdx.x * BLOCK_ROWS;

    for (int kp = 0; kp < D / KT; kp++) {
        __syncthreads();
#pragma unroll
        for (int it = 0; it < 4; it++) {
            int gi  = tid + it * T_TPB;
            int row = gi & 255;
            int c4  = gi >> 8;
            int grow = base_row + row;
            if (grow > N_NODES - 1) grow = N_NODES - 1;
            float4 hv = *reinterpret_cast<const float4*>(
                &h[(size_t)grow * D + kp * KT + c4 * 4]);
            int rp = row + (row >> 3) * 4;
            hT[(c4 * 4 + 0) * HS + rp] = hv.x;
            hT[(c4 * 4 + 1) * HS + rp] = hv.y;
            hT[(c4 * 4 + 2) * HS + rp] = hv.z;
            hT[(c4 * 4 + 3) * HS + rp] = hv.w;
        }
        __syncthreads();

#pragma unroll 4
        for (int kl = 0; kl < KT; kl++) {
            const int k = kp * KT + kl;
            float4 ha = *reinterpret_cast<const float4*>(&hT[kl * HS + rbp]);
            float4 hb = *reinterpret_cast<const float4*>(&hT[kl * HS + rbp + 4]);
            unsigned long long h2[8];
            asm("mov.b64 %0, {%1, %1};" : "=l"(h2[0]) : "r"(__float_as_uint(ha.x)));
            asm("mov.b64 %0, {%1, %1};" : "=l"(h2[1]) : "r"(__float_as_uint(ha.y)));
            asm("mov.b64 %0, {%1, %1};" : "=l"(h2[2]) : "r"(__float_as_uint(ha.z)));
            asm("mov.b64 %0, {%1, %1};" : "=l"(h2[3]) : "r"(__float_as_uint(ha.w)));
            asm("mov.b64 %0, {%1, %1};" : "=l"(h2[4]) : "r"(__float_as_uint(hb.x)));
            asm("mov.b64 %0, {%1, %1};" : "=l"(h2[5]) : "r"(__float_as_uint(hb.y)));
            asm("mov.b64 %0, {%1, %1};" : "=l"(h2[6]) : "r"(__float_as_uint(hb.z)));
            asm("mov.b64 %0, {%1, %1};" : "=l"(h2[7]) : "r"(__float_as_uint(hb.w)));

            ulonglong2 w0 = *reinterpret_cast<const ulonglong2*>(
                &Wt[k * 64 + (cg << 2)]);
            ulonglong2 w1 = *reinterpret_cast<const ulonglong2*>(
                &Wt[k * 64 + ((8 + cg) << 2)]);
#pragma unroll
            for (int i = 0; i < 8; i++) {
                asm("fma.rn.f32x2 %0, %1, %2, %0;"
                    : "+l"(acc[i][0]) : "l"(h2[i]), "l"(w0.x));
                asm("fma.rn.f32x2 %0, %1, %2, %0;"
                    : "+l"(acc[i][1]) : "l"(h2[i]), "l"(w0.y));
                asm("fma.rn.f32x2 %0, %1, %2, %0;"
                    : "+l"(acc[i][2]) : "l"(h2[i]), "l"(w1.x));
                asm("fma.rn.f32x2 %0, %1, %2, %0;"
                    : "+l"(acc[i][3]) : "l"(h2[i]), "l"(w1.y));
            }
        }
    }

    // Epilogue: convert 8 cols (4 f32x2) -> 8 halfs = one uint4 per row.
#pragma unroll
    for (int i = 0; i < 8; i++) {
        int row = row0 + i;
        if (row < N_NODES) {
            uint4 v;
            __half2 p0 = __float22half2_rn(*reinterpret_cast<const float2*>(&acc[i][0]));
            __half2 p1 = __float22half2_rn(*reinterpret_cast<const float2*>(&acc[i][1]));
            __half2 p2 = __float22half2_rn(*reinterpret_cast<const float2*>(&acc[i][2]));
            __half2 p3 = __float22half2_rn(*reinterpret_cast<const float2*>(&acc[i][3]));
            v.x = *reinterpret_cast<const unsigned int*>(&p0);
            v.y = *reinterpret_cast<const unsigned int*>(&p1);
            v.z = *reinterpret_cast<const unsigned int*>(&p2);
            v.w = *reinterpret_cast<const unsigned int*>(&p3);
            *reinterpret_cast<uint4*>(&g_feat[(size_t)row * D + cg * 8]) = v;
        }
    }
}

// ---------------------------------------------------------------------------
// Aggregate: out[n] = b + sum_{edges->n} g[src]*e.
// 8 threads per node, thread = (node, 8-half-col chunk). One uint4 (16B)
// gather per edge per thread -> whole warp touches ONE 128B line per edge.
// fp32 accumulation, unroll-2 (R12-proven control flow).
// ---------------------------------------------------------------------------
__global__ __launch_bounds__(256) void aggregate_kernel(
        const float* __restrict__ bias, float* __restrict__ out) {
    int t = blockIdx.x * 256 + threadIdx.x;       // grid exactly N_NODES*8
    int node = t >> 3;
    int q    = (t & 7) * 8;                       // half-column base

    float4 acc0 = __ldg(reinterpret_cast<const float4*>(&bias[q]));
    float4 acc1 = __ldg(reinterpret_cast<const float4*>(&bias[q + 4]));

    int i   = offs[node];
    int end = offs[node + 1];

    for (; i + 2 <= end; i += 2) {
        int2 p0 = edge_s[i];
        int2 p1 = edge_s[i + 1];
        uint4 ga = *reinterpret_cast<const uint4*>(&g_feat[(size_t)p0.x * D + q]);
        uint4 gb = *reinterpret_cast<const uint4*>(&g_feat[(size_t)p1.x * D + q]);
        float e0 = __int_as_float(p0.y), e1 = __int_as_float(p1.y);

        float2 a0 = __half22float2(*reinterpret_cast<const __half2*>(&ga.x));
        float2 a1 = __half22float2(*reinterpret_cast<const __half2*>(&ga.y));
        float2 a2 = __half22float2(*reinterpret_cast<const __half2*>(&ga.z));
        float2 a3 = __half22float2(*reinterpret_cast<const __half2*>(&ga.w));
        acc0.x = fmaf(a0.x, e0, acc0.x); acc0.y = fmaf(a0.y, e0, acc0.y);
        acc0.z = fmaf(a1.x, e0, acc0.z); acc0.w = fmaf(a1.y, e0, acc0.w);
        acc1.x = fmaf(a2.x, e0, acc1.x); acc1.y = fmaf(a2.y, e0, acc1.y);
        acc1.z = fmaf(a3.x, e0, acc1.z); acc1.w = fmaf(a3.y, e0, acc1.w);

        float2 b0 = __half22float2(*reinterpret_cast<const __half2*>(&gb.x));
        float2 b1 = __half22float2(*reinterpret_cast<const __half2*>(&gb.y));
        float2 b2 = __half22float2(*reinterpret_cast<const __half2*>(&gb.z));
        float2 b3 = __half22float2(*reinterpret_cast<const __half2*>(&gb.w));
        acc0.x = fmaf(b0.x, e1, acc0.x); acc0.y = fmaf(b0.y, e1, acc0.y);
        acc0.z = fmaf(b1.x, e1, acc0.z); acc0.w = fmaf(b1.y, e1, acc0.w);
        acc1.x = fmaf(b2.x, e1, acc1.x); acc1.y = fmaf(b2.y, e1, acc1.y);
        acc1.z = fmaf(b3.x, e1, acc1.z); acc1.w = fmaf(b3.y, e1, acc1.w);
    }
    if (i < end) {
        int2 p0 = edge_s[i];
        uint4 ga = *reinterpret_cast<const uint4*>(&g_feat[(size_t)p0.x * D + q]);
        float e0 = __int_as_float(p0.y);
        float2 a0 = __half22float2(*reinterpret_cast<const __half2*>(&ga.x));
        float2 a1 = __half22float2(*reinterpret_cast<const __half2*>(&ga.y));
        float2 a2 = __half22float2(*reinterpret_cast<const __half2*>(&ga.z));
        float2 a3 = __half22float2(*reinterpret_cast<const __half2*>(&ga.w));
        acc0.x = fmaf(a0.x, e0, acc0.x); acc0.y = fmaf(a0.y, e0, acc0.y);
        acc0.z = fmaf(a1.x, e0, acc0.z); acc0.w = fmaf(a1.y, e0, acc0.w);
        acc1.x = fmaf(a2.x, e0, acc1.x); acc1.y = fmaf(a2.y, e0, acc1.y);
        acc1.z = fmaf(a3.x, e0, acc1.z); acc1.w = fmaf(a3.y, e0, acc1.w);
    }

    float* op = &out[(size_t)node * D + q];
    *reinterpret_cast<float4*>(op)     = acc0;
    *reinterpret_cast<float4*>(op + 4) = acc1;
}

// ---------------------------------------------------------------------------
extern "C" void kernel_launch(void* const* d_in, const int* in_sizes, int n_in,
                              void* d_out, int out_size) {
    const float* h   = (const float*)d_in[0];
    const float* e   = (const float*)d_in[1];
    const int*   src = (const int*)d_in[2];
    const int*   dst = (const int*)d_in[3];
    const float* W   = (const float*)d_in[4];
    const float* b   = (const float*)d_in[5];
    float*       out = (float*)d_out;

    const int eb = (N_EDGES + 255) / 256;          // 4883

    // Fork: CSR build on side stream, transform on main stream (independent).
    cudaEventRecord(g_fork, 0);
    cudaStreamWaitEvent(g_side, g_fork, 0);

    zero_deg_kernel<<<NB, 256, 0, g_side>>>();
    hist_kernel<<<eb, 256, 0, g_side>>>(dst);
    partial_kernel<<<NB, 256, 0, g_side>>>();
    scan_partials_kernel<<<1, 512, 0, g_side>>>();
    offsets_kernel<<<NB, 256, 0, g_side>>>();
    place_kernel<<<eb, 256, 0, g_side>>>(e, src, dst);
    cudaEventRecord(g_join, g_side);

    // g = h @ W^T  (main stream, overlaps with CSR build)
    transform_kernel<<<NB, T_TPB>>>(h, W);

    // Join, then aggregate: out = b + segment_sum(g[src] * e)
    cudaStreamWaitEvent(0, g_join, 0);
    aggregate_kernel<<<(N_NODES * 8) / 256, 256>>>(b, out);
}